// round 1
// baseline (speedup 1.0000x reference)
#include <cuda_runtime.h>

#define NN 100000
#define EE_MAX 3200000

// ---------------- device scratch (static, allocation-free) ----------------
__device__ float g_h1[NN * 64];     // layer1 transformed features [N,8,8]
__device__ float g_as1[NN * 8];     // alpha_src per node per head
__device__ float g_ad1[NN * 8];     // alpha_dst per node per head
__device__ float g_agg1[NN * 64];   // numerator accumulator -> becomes out1
__device__ float g_den1[NN * 8];    // denominator accumulator
__device__ float g_h2[NN * 8];      // layer2 features [N,7] + ones slot [7]=1
__device__ float g_as2[NN];
__device__ float g_ad2[NN];
__device__ float g_agg2[NN * 8];    // numerator [0..6] + denominator [7]

__device__ __forceinline__ float lrexp(float x) {
    // exp(leaky_relu(x, 0.2)); values are O(1) so no max-subtraction needed
    x = x > 0.0f ? x : 0.2f * x;
    return __expf(x);
}

__device__ __forceinline__ void atomic_add_f4(float4* p, float4 v) {
    atomicAdd(p, v);   // sm_90+ vector atomic (compiled for sm_103a)
}

// ---------------- zero scratch accumulators ----------------
__global__ void zero_kernel() {
    int i = blockIdx.x * blockDim.x + threadIdx.x;
    int stride = gridDim.x * blockDim.x;
    float4 z = make_float4(0.f, 0.f, 0.f, 0.f);
    float4* a = (float4*)g_agg1;
    for (int j = i; j < NN * 16; j += stride) a[j] = z;
    float4* b = (float4*)g_den1;
    for (int j = i; j < NN * 2; j += stride) b[j] = z;
    float4* c = (float4*)g_agg2;
    for (int j = i; j < NN * 2; j += stride) c[j] = z;
}

// ---------------- SGEMM1: h1 = x @ W1   [N,512]x[512,64] ----------------
__global__ __launch_bounds__(256) void sgemm1_kernel(const float* __restrict__ A,
                                                     const float* __restrict__ B) {
    __shared__ float As[32][132];   // [k][row], padded
    __shared__ float Bs[32][64];    // [k][col]
    int t = threadIdx.x;
    int tx = t & 15, ty = t >> 4;
    int row0 = blockIdx.x * 128;
    float acc[8][4];
#pragma unroll
    for (int i = 0; i < 8; i++)
#pragma unroll
        for (int j = 0; j < 4; j++) acc[i][j] = 0.f;

    for (int kk = 0; kk < 512; kk += 32) {
#pragma unroll
        for (int j = 0; j < 4; j++) {
            int idx = t + j * 256;       // 0..1023
            int r = idx >> 3;            // row in tile
            int kq = idx & 7;            // float4 index along k
            float4 v = make_float4(0.f, 0.f, 0.f, 0.f);
            if (row0 + r < NN)
                v = *reinterpret_cast<const float4*>(A + (size_t)(row0 + r) * 512 + kk + kq * 4);
            As[kq * 4 + 0][r] = v.x;
            As[kq * 4 + 1][r] = v.y;
            As[kq * 4 + 2][r] = v.z;
            As[kq * 4 + 3][r] = v.w;
        }
#pragma unroll
        for (int j = 0; j < 2; j++) {
            int idx = t + j * 256;       // 0..511
            int r = idx >> 4;            // k-row
            int cq = idx & 15;           // float4 col index
            float4 v = *reinterpret_cast<const float4*>(B + (size_t)(kk + r) * 64 + cq * 4);
            *reinterpret_cast<float4*>(&Bs[r][cq * 4]) = v;
        }
        __syncthreads();
#pragma unroll
        for (int k = 0; k < 32; k++) {
            float a[8], bb[4];
#pragma unroll
            for (int i = 0; i < 8; i++) a[i] = As[k][ty * 8 + i];
#pragma unroll
            for (int j = 0; j < 4; j++) bb[j] = Bs[k][tx * 4 + j];
#pragma unroll
            for (int i = 0; i < 8; i++)
#pragma unroll
                for (int j = 0; j < 4; j++) acc[i][j] += a[i] * bb[j];
        }
        __syncthreads();
    }
#pragma unroll
    for (int i = 0; i < 8; i++) {
        int r = row0 + ty * 8 + i;
        if (r < NN)
            *reinterpret_cast<float4*>(g_h1 + (size_t)r * 64 + tx * 4) =
                make_float4(acc[i][0], acc[i][1], acc[i][2], acc[i][3]);
    }
}

// ---------------- per-(node,head) attention logits ----------------
__global__ void alpha1_kernel(const float* __restrict__ a_src,
                              const float* __restrict__ a_dst) {
    int i = blockIdx.x * blockDim.x + threadIdx.x;
    if (i >= NN * 8) return;
    int n = i >> 3, h = i & 7;
    const float* hp = g_h1 + (size_t)n * 64 + h * 8;
    const float* asp = a_src + h * 8;
    const float* adp = a_dst + h * 8;
    float s = 0.f, d = 0.f;
#pragma unroll
    for (int c = 0; c < 8; c++) {
        float v = hp[c];
        s += v * asp[c];
        d += v * adp[c];
    }
    g_as1[i] = s;
    g_ad1[i] = d;
}

// ---------------- layer-1 edge pass (fused exp + weighted scatter) ----------
__global__ __launch_bounds__(128) void edge1_kernel(const int* __restrict__ src,
                                                    const int* __restrict__ dst, int E) {
    int e = blockIdx.x * blockDim.x + threadIdx.x;
    if (e >= E) return;
    int s = src[e], d = dst[e];
    float4 s0 = ((const float4*)g_as1)[s * 2];
    float4 s1 = ((const float4*)g_as1)[s * 2 + 1];
    float4 d0 = ((const float4*)g_ad1)[d * 2];
    float4 d1 = ((const float4*)g_ad1)[d * 2 + 1];
    float w[8];
    w[0] = lrexp(s0.x + d0.x);
    w[1] = lrexp(s0.y + d0.y);
    w[2] = lrexp(s0.z + d0.z);
    w[3] = lrexp(s0.w + d0.w);
    w[4] = lrexp(s1.x + d1.x);
    w[5] = lrexp(s1.y + d1.y);
    w[6] = lrexp(s1.z + d1.z);
    w[7] = lrexp(s1.w + d1.w);
    atomic_add_f4((float4*)g_den1 + d * 2, make_float4(w[0], w[1], w[2], w[3]));
    atomic_add_f4((float4*)g_den1 + d * 2 + 1, make_float4(w[4], w[5], w[6], w[7]));
    const float4* hv = (const float4*)g_h1 + (size_t)s * 16;
    float4* av = (float4*)g_agg1 + (size_t)d * 16;
#pragma unroll
    for (int h = 0; h < 8; h++) {
        float4 v0 = hv[2 * h], v1 = hv[2 * h + 1];
        float ww = w[h];
        atomic_add_f4(av + 2 * h, make_float4(v0.x * ww, v0.y * ww, v0.z * ww, v0.w * ww));
        atomic_add_f4(av + 2 * h + 1, make_float4(v1.x * ww, v1.y * ww, v1.z * ww, v1.w * ww));
    }
}

// ---------------- layer-1 finalize: add self-loop, divide, bias ------------
__global__ void fin1_kernel(const float* __restrict__ b1) {
    int i = blockIdx.x * blockDim.x + threadIdx.x;
    if (i >= NN * 8) return;
    int n = i >> 3, h = i & 7;
    float e = g_as1[i] + g_ad1[i];
    e = e > 0.f ? e : 0.2f * e;
    float w = __expf(e);
    float inv = 1.0f / (g_den1[i] + w + 1e-16f);
    size_t base = (size_t)n * 64 + h * 8;
    float4* agg = (float4*)(g_agg1 + base);
    const float4* hv = (const float4*)(g_h1 + base);
    const float4* bb = (const float4*)(b1 + h * 8);
#pragma unroll
    for (int q = 0; q < 2; q++) {
        float4 a = agg[q], x = hv[q], bv = bb[q];
        a.x = (a.x + w * x.x) * inv + bv.x;
        a.y = (a.y + w * x.y) * inv + bv.y;
        a.z = (a.z + w * x.z) * inv + bv.z;
        a.w = (a.w + w * x.w) * inv + bv.w;
        agg[q] = a;
    }
}

// ---------------- layer-2 transform: h2 = out1 @ W2, alphas ----------------
__global__ __launch_bounds__(128) void gemm2_kernel(const float* __restrict__ W2,
                                                    const float* __restrict__ a_src,
                                                    const float* __restrict__ a_dst) {
    __shared__ float sW[448];
    __shared__ float sa[7], sd[7];
    int t = threadIdx.x;
    for (int j = t; j < 448; j += blockDim.x) sW[j] = W2[j];
    if (t < 7) { sa[t] = a_src[t]; sd[t] = a_dst[t]; }
    __syncthreads();
    int n = blockIdx.x * blockDim.x + t;
    if (n >= NN) return;
    float v[64];
    const float4* row = (const float4*)g_agg1 + (size_t)n * 16;
#pragma unroll
    for (int q = 0; q < 16; q++) {
        float4 x = row[q];
        v[4 * q] = x.x; v[4 * q + 1] = x.y; v[4 * q + 2] = x.z; v[4 * q + 3] = x.w;
    }
    float h[7] = {0.f, 0.f, 0.f, 0.f, 0.f, 0.f, 0.f};
#pragma unroll 8
    for (int k = 0; k < 64; k++) {
        float vk = v[k];
#pragma unroll
        for (int c = 0; c < 7; c++) h[c] += vk * sW[k * 7 + c];
    }
    float s = 0.f, d = 0.f;
#pragma unroll
    for (int c = 0; c < 7; c++) { s += h[c] * sa[c]; d += h[c] * sd[c]; }
    float* hp = g_h2 + (size_t)n * 8;
#pragma unroll
    for (int c = 0; c < 7; c++) hp[c] = h[c];
    hp[7] = 1.0f;    // ones slot -> denominator accumulates in agg2[7]
    g_as2[n] = s;
    g_ad2[n] = d;
}

// ---------------- layer-2 edge pass ----------------
__global__ __launch_bounds__(256) void edge2_kernel(const int* __restrict__ src,
                                                    const int* __restrict__ dst, int E) {
    int e = blockIdx.x * blockDim.x + threadIdx.x;
    if (e >= E) return;
    int s = src[e], d = dst[e];
    float w = lrexp(g_as2[s] + g_ad2[d]);
    float4 v0 = ((const float4*)g_h2)[s * 2];
    float4 v1 = ((const float4*)g_h2)[s * 2 + 1];
    atomic_add_f4((float4*)g_agg2 + d * 2, make_float4(v0.x * w, v0.y * w, v0.z * w, v0.w * w));
    atomic_add_f4((float4*)g_agg2 + d * 2 + 1, make_float4(v1.x * w, v1.y * w, v1.z * w, v1.w * w));
}

// ---------------- layer-2 finalize + log_softmax ----------------
__global__ void fin2_kernel(const float* __restrict__ b2, float* __restrict__ out) {
    int n = blockIdx.x * blockDim.x + threadIdx.x;
    if (n >= NN) return;
    float e = g_as2[n] + g_ad2[n];
    e = e > 0.f ? e : 0.2f * e;
    float w = __expf(e);
    const float* a = g_agg2 + (size_t)n * 8;
    const float* hv = g_h2 + (size_t)n * 8;
    float num[8];
#pragma unroll
    for (int j = 0; j < 8; j++) num[j] = a[j] + w * hv[j];
    float inv = 1.0f / (num[7] + 1e-16f);
    float o[7], m = -1e30f;
#pragma unroll
    for (int c = 0; c < 7; c++) {
        o[c] = num[c] * inv + b2[c];
        m = fmaxf(m, o[c]);
    }
    float sum = 0.f;
#pragma unroll
    for (int c = 0; c < 7; c++) sum += __expf(o[c] - m);
    float lse = m + logf(sum);
#pragma unroll
    for (int c = 0; c < 7; c++) out[(size_t)n * 7 + c] = o[c] - lse;
}

// ---------------- launcher ----------------
extern "C" void kernel_launch(void* const* d_in, const int* in_sizes, int n_in,
                              void* d_out, int out_size) {
    const float* x    = (const float*)d_in[0];
    const int*   ei   = (const int*)d_in[1];
    const float* W1   = (const float*)d_in[2];
    const float* as1  = (const float*)d_in[3];
    const float* ad1  = (const float*)d_in[4];
    const float* b1   = (const float*)d_in[5];
    const float* W2   = (const float*)d_in[6];
    const float* as2  = (const float*)d_in[7];
    const float* ad2  = (const float*)d_in[8];
    const float* b2   = (const float*)d_in[9];
    float* out = (float*)d_out;
    int E = in_sizes[1] / 2;

    zero_kernel<<<2048, 256>>>();
    sgemm1_kernel<<<(NN + 127) / 128, 256>>>(x, W1);
    alpha1_kernel<<<(NN * 8 + 255) / 256, 256>>>(as1, ad1);
    edge1_kernel<<<(E + 127) / 128, 128>>>(ei, ei + E, E);
    fin1_kernel<<<(NN * 8 + 255) / 256, 256>>>(b1);
    gemm2_kernel<<<(NN + 127) / 128, 128>>>(W2, as2, ad2);
    edge2_kernel<<<(E + 255) / 256, 256>>>(ei, ei + E, E);
    fin2_kernel<<<(NN + 255) / 256, 256>>>(b2, out);
}

// round 4
// speedup vs baseline: 1.7747x; 1.7747x over previous
#include <cuda_runtime.h>

#define NN 100000
#define EE_MAX 3200000
#define SCAN_BLK 1024
#define NBLK ((NN + SCAN_BLK - 1) / SCAN_BLK)   // 98

// ---------------- device scratch (static, allocation-free) ----------------
__device__ float g_h1[NN * 64];     // layer1 transformed features [N,8,8]
__device__ float g_as1[NN * 8];
__device__ float g_ad1[NN * 8];
__device__ float g_out1[NN * 64];   // layer1 output
__device__ float g_h2[NN * 8];      // layer2 features [N,7] + ones slot
__device__ float g_as2[NN];
__device__ float g_ad2[NN];

__device__ int g_cnt[NN];           // in-degree
__device__ int g_start[NN];         // CSR row start
__device__ int g_cursor[NN];        // scatter cursor
__device__ int g_bsum[NBLK];        // block sums for scan
__device__ int g_csr[EE_MAX];       // src ids sorted by dst

__device__ __forceinline__ float lrexp(float x) {
    x = x > 0.0f ? x : 0.2f * x;
    return __expf(x);
}

// ---------------- CSR build ----------------
__global__ void zero_cnt_kernel() {
    int i = blockIdx.x * blockDim.x + threadIdx.x;
    if (i < NN) g_cnt[i] = 0;
}

__global__ void hist_kernel(const int* __restrict__ dst, int E) {
    int e = blockIdx.x * blockDim.x + threadIdx.x;
    if (e < E) atomicAdd(&g_cnt[dst[e]], 1);
}

// per-block exclusive scan of 1024 counts -> g_start (local), block total -> g_bsum
__global__ __launch_bounds__(256) void scan1_kernel() {
    __shared__ int warp_tot[8];
    int b = blockIdx.x, t = threadIdx.x;
    int base = b * SCAN_BLK + t * 4;
    int v[4];
#pragma unroll
    for (int k = 0; k < 4; k++) v[k] = (base + k < NN) ? g_cnt[base + k] : 0;
    int tsum = v[0] + v[1] + v[2] + v[3];
    // warp inclusive scan of tsum
    int lane = t & 31, wid = t >> 5;
    int inc = tsum;
#pragma unroll
    for (int off = 1; off < 32; off <<= 1) {
        int n = __shfl_up_sync(0xffffffffu, inc, off);
        if (lane >= off) inc += n;
    }
    if (lane == 31) warp_tot[wid] = inc;
    __syncthreads();
    if (wid == 0) {
        int w = (lane < 8) ? warp_tot[lane] : 0;
#pragma unroll
        for (int off = 1; off < 8; off <<= 1) {
            int n = __shfl_up_sync(0xffffffffu, w, off);
            if (lane >= off) w += n;
        }
        if (lane < 8) warp_tot[lane] = w;
    }
    __syncthreads();
    int excl = inc - tsum + (wid > 0 ? warp_tot[wid - 1] : 0);
#pragma unroll
    for (int k = 0; k < 4; k++) {
        if (base + k < NN) g_start[base + k] = excl;
        excl += v[k];
    }
    if (t == 255) g_bsum[b] = excl;   // block total (inclusive over block)
}

__global__ void scan2_kernel() {   // single thread: exclusive scan of 98 block sums
    if (threadIdx.x == 0 && blockIdx.x == 0) {
        int acc = 0;
        for (int b = 0; b < NBLK; b++) {
            int v = g_bsum[b];
            g_bsum[b] = acc;
            acc += v;
        }
    }
}

__global__ void scan3_kernel() {
    int i = blockIdx.x * blockDim.x + threadIdx.x;
    if (i < NN) {
        int s = g_start[i] + g_bsum[i / SCAN_BLK];
        g_start[i] = s;
        g_cursor[i] = s;
    }
}

__global__ void scatter_kernel(const int* __restrict__ src,
                               const int* __restrict__ dst, int E) {
    int e = blockIdx.x * blockDim.x + threadIdx.x;
    if (e < E) {
        int pos = atomicAdd(&g_cursor[dst[e]], 1);
        g_csr[pos] = src[e];
    }
}

// ---------------- SGEMM1: h1 = x @ W1   [N,512]x[512,64] ----------------
__global__ __launch_bounds__(256) void sgemm1_kernel(const float* __restrict__ A,
                                                     const float* __restrict__ B) {
    __shared__ float As[32][132];
    __shared__ float Bs[32][64];
    int t = threadIdx.x;
    int tx = t & 15, ty = t >> 4;
    int row0 = blockIdx.x * 128;
    float acc[8][4];
#pragma unroll
    for (int i = 0; i < 8; i++)
#pragma unroll
        for (int j = 0; j < 4; j++) acc[i][j] = 0.f;

    for (int kk = 0; kk < 512; kk += 32) {
#pragma unroll
        for (int j = 0; j < 4; j++) {
            int idx = t + j * 256;
            int r = idx >> 3;
            int kq = idx & 7;
            float4 v = make_float4(0.f, 0.f, 0.f, 0.f);
            if (row0 + r < NN)
                v = *reinterpret_cast<const float4*>(A + (size_t)(row0 + r) * 512 + kk + kq * 4);
            As[kq * 4 + 0][r] = v.x;
            As[kq * 4 + 1][r] = v.y;
            As[kq * 4 + 2][r] = v.z;
            As[kq * 4 + 3][r] = v.w;
        }
#pragma unroll
        for (int j = 0; j < 2; j++) {
            int idx = t + j * 256;
            int r = idx >> 4;
            int cq = idx & 15;
            float4 v = *reinterpret_cast<const float4*>(B + (size_t)(kk + r) * 64 + cq * 4);
            *reinterpret_cast<float4*>(&Bs[r][cq * 4]) = v;
        }
        __syncthreads();
#pragma unroll
        for (int k = 0; k < 32; k++) {
            float a[8], bb[4];
#pragma unroll
            for (int i = 0; i < 8; i++) a[i] = As[k][ty * 8 + i];
#pragma unroll
            for (int j = 0; j < 4; j++) bb[j] = Bs[k][tx * 4 + j];
#pragma unroll
            for (int i = 0; i < 8; i++)
#pragma unroll
                for (int j = 0; j < 4; j++) acc[i][j] += a[i] * bb[j];
        }
        __syncthreads();
    }
#pragma unroll
    for (int i = 0; i < 8; i++) {
        int r = row0 + ty * 8 + i;
        if (r < NN)
            *reinterpret_cast<float4*>(g_h1 + (size_t)r * 64 + tx * 4) =
                make_float4(acc[i][0], acc[i][1], acc[i][2], acc[i][3]);
    }
}

// ---------------- attention logits layer 1 ----------------
__global__ void alpha1_kernel(const float* __restrict__ a_src,
                              const float* __restrict__ a_dst) {
    int i = blockIdx.x * blockDim.x + threadIdx.x;
    if (i >= NN * 8) return;
    int n = i >> 3, h = i & 7;
    const float* hp = g_h1 + (size_t)n * 64 + h * 8;
    const float* asp = a_src + h * 8;
    const float* adp = a_dst + h * 8;
    float s = 0.f, d = 0.f;
#pragma unroll
    for (int c = 0; c < 8; c++) {
        float v = hp[c];
        s += v * asp[c];
        d += v * adp[c];
    }
    g_as1[i] = s;
    g_ad1[i] = d;
}

// ---------------- layer-1 gather: one warp per dst node (fused finalize) ----
__global__ __launch_bounds__(256) void gather1_kernel(const float* __restrict__ b1) {
    int warp_id = (blockIdx.x * blockDim.x + threadIdx.x) >> 5;
    if (warp_id >= NN) return;
    int l = threadIdx.x & 31;
    int n = warp_id;
    int h = l >> 2;                       // head handled by this lane's channels
    float ad_h = g_ad1[n * 8 + h];
    int st = g_start[n];
    int deg = g_cnt[n];
    float acc0 = 0.f, acc1 = 0.f, den = 0.f;
    for (int i = 0; i < deg; i++) {
        int s = g_csr[st + i];            // broadcast across warp
        float w = lrexp(g_as1[s * 8 + h] + ad_h);
        float2 hv = *reinterpret_cast<const float2*>(g_h1 + (size_t)s * 64 + 2 * l);
        acc0 += w * hv.x;
        acc1 += w * hv.y;
        if ((l & 3) == 0) den += w;
    }
    // self loop
    float wself = lrexp(g_as1[n * 8 + h] + ad_h);
    float2 hs = *reinterpret_cast<const float2*>(g_h1 + (size_t)n * 64 + 2 * l);
    acc0 += wself * hs.x;
    acc1 += wself * hs.y;
    if ((l & 3) == 0) den += wself;
    float den_all = __shfl_sync(0xffffffffu, den, l & ~3);
    float inv = 1.0f / (den_all + 1e-16f);
    float2 bv = *reinterpret_cast<const float2*>(b1 + 2 * l);
    float2 o = make_float2(acc0 * inv + bv.x, acc1 * inv + bv.y);
    *reinterpret_cast<float2*>(g_out1 + (size_t)n * 64 + 2 * l) = o;
}

// ---------------- layer-2 transform ----------------
__global__ __launch_bounds__(128) void gemm2_kernel(const float* __restrict__ W2,
                                                    const float* __restrict__ a_src,
                                                    const float* __restrict__ a_dst) {
    __shared__ float sW[448];
    __shared__ float sa[7], sd[7];
    int t = threadIdx.x;
    for (int j = t; j < 448; j += blockDim.x) sW[j] = W2[j];
    if (t < 7) { sa[t] = a_src[t]; sd[t] = a_dst[t]; }
    __syncthreads();
    int n = blockIdx.x * blockDim.x + t;
    if (n >= NN) return;
    float v[64];
    const float4* row = (const float4*)g_out1 + (size_t)n * 16;
#pragma unroll
    for (int q = 0; q < 16; q++) {
        float4 x = row[q];
        v[4 * q] = x.x; v[4 * q + 1] = x.y; v[4 * q + 2] = x.z; v[4 * q + 3] = x.w;
    }
    float h[7] = {0.f, 0.f, 0.f, 0.f, 0.f, 0.f, 0.f};
#pragma unroll 8
    for (int k = 0; k < 64; k++) {
        float vk = v[k];
#pragma unroll
        for (int c = 0; c < 7; c++) h[c] += vk * sW[k * 7 + c];
    }
    float s = 0.f, d = 0.f;
#pragma unroll
    for (int c = 0; c < 7; c++) { s += h[c] * sa[c]; d += h[c] * sd[c]; }
    float* hp = g_h2 + (size_t)n * 8;
#pragma unroll
    for (int c = 0; c < 7; c++) hp[c] = h[c];
    hp[7] = 1.0f;   // ones slot -> denominator
    g_as2[n] = s;
    g_ad2[n] = d;
}

// ---------------- layer-2 gather (fused finalize + log_softmax) ------------
// 8 lanes per dst node; warp handles 4 nodes
__global__ __launch_bounds__(256) void gather2_kernel(const float* __restrict__ b2,
                                                      float* __restrict__ out) {
    int gid = blockIdx.x * blockDim.x + threadIdx.x;
    int n = gid >> 3;
    if (n >= NN) return;
    int c = gid & 7;
    float ad = g_ad2[n];
    int st = g_start[n];
    int deg = g_cnt[n];
    float acc = 0.f;
    for (int i = 0; i < deg; i++) {
        int s = g_csr[st + i];
        float w = lrexp(g_as2[s] + ad);
        acc += w * g_h2[(size_t)s * 8 + c];
    }
    float wself = lrexp(g_as2[n] + ad);
    acc += wself * g_h2[(size_t)n * 8 + c];
    // lane c==7 holds denominator
    float den = __shfl_sync(0xffffffffu, acc, (threadIdx.x & ~7) | 7);
    float inv = 1.0f / (den + 1e-16f);
    float o = (c < 7) ? (acc * inv + b2[c]) : -1e30f;
    // 8-lane max
    float m = o;
#pragma unroll
    for (int off = 1; off < 8; off <<= 1)
        m = fmaxf(m, __shfl_xor_sync(0xffffffffu, m, off));
    float ex = (c < 7) ? __expf(o - m) : 0.f;
    float sum = ex;
#pragma unroll
    for (int off = 1; off < 8; off <<= 1)
        sum += __shfl_xor_sync(0xffffffffu, sum, off);
    float lse = m + logf(sum);
    if (c < 7) out[(size_t)n * 7 + c] = o - lse;
}

// ---------------- launcher ----------------
extern "C" void kernel_launch(void* const* d_in, const int* in_sizes, int n_in,
                              void* d_out, int out_size) {
    const float* x    = (const float*)d_in[0];
    const int*   ei   = (const int*)d_in[1];
    const float* W1   = (const float*)d_in[2];
    const float* as1  = (const float*)d_in[3];
    const float* ad1  = (const float*)d_in[4];
    const float* b1   = (const float*)d_in[5];
    const float* W2   = (const float*)d_in[6];
    const float* as2  = (const float*)d_in[7];
    const float* ad2  = (const float*)d_in[8];
    const float* b2   = (const float*)d_in[9];
    float* out = (float*)d_out;
    int E = in_sizes[1] / 2;
    const int* src = ei;
    const int* dst = ei + E;

    zero_cnt_kernel<<<(NN + 255) / 256, 256>>>();
    hist_kernel<<<(E + 255) / 256, 256>>>(dst, E);
    scan1_kernel<<<NBLK, 256>>>();
    scan2_kernel<<<1, 32>>>();
    scan3_kernel<<<(NN + 255) / 256, 256>>>();
    scatter_kernel<<<(E + 255) / 256, 256>>>(src, dst, E);

    sgemm1_kernel<<<(NN + 127) / 128, 256>>>(x, W1);
    alpha1_kernel<<<(NN * 8 + 255) / 256, 256>>>(as1, ad1);
    gather1_kernel<<<(NN * 32 + 255) / 256, 256>>>(b1);
    gemm2_kernel<<<(NN + 127) / 128, 128>>>(W2, as2, ad2);
    gather2_kernel<<<(NN * 8 + 255) / 256, 256>>>(b2, out);
}

// round 6
// speedup vs baseline: 2.3423x; 1.3198x over previous
#include <cuda_runtime.h>
#include <cstdint>

#define NN 100000
#define EE_MAX 3200000
#define SCAN_BLK 1024
#define NBLK ((NN + SCAN_BLK - 1) / SCAN_BLK)   // 98

// ---------------- device scratch (static, allocation-free) ----------------
__device__ float g_h1[NN * 64];     // layer1 transformed features [N,8,8]
__device__ float g_as1[NN * 8];
__device__ float g_ad1[NN * 8];
__device__ float g_out1[NN * 64];   // layer1 output
__device__ float g_h2[NN * 8];      // layer2 features [N,7] + ones slot
__device__ float g_as2[NN];
__device__ float g_ad2[NN];
__device__ float g_W1t[64 * 512];   // W1 transposed [N=64][K=512]

__device__ int g_cnt[NN];           // in-degree
__device__ int g_start[NN];         // CSR row start
__device__ int g_cursor[NN];        // scatter cursor
__device__ int g_bsum[NBLK];        // block sums for scan
__device__ int g_csr[EE_MAX];       // src ids sorted by dst

__device__ __forceinline__ float lrexp(float x) {
    x = x > 0.0f ? x : 0.2f * x;
    return __expf(x);
}

__device__ __forceinline__ uint32_t f2tf32(float f) {
    uint32_t u;
    asm("cvt.rna.tf32.f32 %0, %1;" : "=r"(u) : "f"(f));
    return u;
}

__device__ __forceinline__ void mma_tf32(float& c0, float& c1, float& c2, float& c3,
                                         uint32_t a0, uint32_t a1, uint32_t a2, uint32_t a3,
                                         uint32_t b0, uint32_t b1) {
    asm volatile(
        "mma.sync.aligned.m16n8k8.row.col.f32.tf32.tf32.f32 "
        "{%0,%1,%2,%3}, {%4,%5,%6,%7}, {%8,%9}, {%0,%1,%2,%3};"
        : "+f"(c0), "+f"(c1), "+f"(c2), "+f"(c3)
        : "r"(a0), "r"(a1), "r"(a2), "r"(a3), "r"(b0), "r"(b1));
}

// ---------------- CSR build ----------------
__global__ void zero_cnt_kernel() {
    int i = blockIdx.x * blockDim.x + threadIdx.x;
    if (i < NN) g_cnt[i] = 0;
}

__global__ void hist_kernel(const int* __restrict__ dst, int E) {
    int e = blockIdx.x * blockDim.x + threadIdx.x;
    if (e < E) atomicAdd(&g_cnt[dst[e]], 1);
}

__global__ __launch_bounds__(256) void scan1_kernel() {
    __shared__ int warp_tot[8];
    int b = blockIdx.x, t = threadIdx.x;
    int base = b * SCAN_BLK + t * 4;
    int v[4];
#pragma unroll
    for (int k = 0; k < 4; k++) v[k] = (base + k < NN) ? g_cnt[base + k] : 0;
    int tsum = v[0] + v[1] + v[2] + v[3];
    int lane = t & 31, wid = t >> 5;
    int inc = tsum;
#pragma unroll
    for (int off = 1; off < 32; off <<= 1) {
        int n = __shfl_up_sync(0xffffffffu, inc, off);
        if (lane >= off) inc += n;
    }
    if (lane == 31) warp_tot[wid] = inc;
    __syncthreads();
    if (wid == 0) {
        int w = (lane < 8) ? warp_tot[lane] : 0;
#pragma unroll
        for (int off = 1; off < 8; off <<= 1) {
            int n = __shfl_up_sync(0xffffffffu, w, off);
            if (lane >= off) w += n;
        }
        if (lane < 8) warp_tot[lane] = w;
    }
    __syncthreads();
    int excl = inc - tsum + (wid > 0 ? warp_tot[wid - 1] : 0);
#pragma unroll
    for (int k = 0; k < 4; k++) {
        if (base + k < NN) g_start[base + k] = excl;
        excl += v[k];
    }
    if (t == 255) g_bsum[b] = excl;
}

__global__ void scan2_kernel() {   // parallel exclusive scan of 98 block sums
    __shared__ int s[128];
    int t = threadIdx.x;
    int v = (t < NBLK) ? g_bsum[t] : 0;
    s[t] = v;
    __syncthreads();
#pragma unroll
    for (int off = 1; off < 128; off <<= 1) {
        int x = (t >= off) ? s[t - off] : 0;
        __syncthreads();
        s[t] += x;
        __syncthreads();
    }
    if (t < NBLK) g_bsum[t] = s[t] - v;   // exclusive
}

__global__ void scan3_kernel() {
    int i = blockIdx.x * blockDim.x + threadIdx.x;
    if (i < NN) {
        int s = g_start[i] + g_bsum[i / SCAN_BLK];
        g_start[i] = s;
        g_cursor[i] = s;
    }
}

__global__ void scatter_kernel(const int* __restrict__ src,
                               const int* __restrict__ dst, int E) {
    int e = blockIdx.x * blockDim.x + threadIdx.x;
    if (e < E) {
        int pos = atomicAdd(&g_cursor[dst[e]], 1);
        g_csr[pos] = src[e];
    }
}

// ---------------- W1 transpose ----------------
__global__ void transposeW1_kernel(const float* __restrict__ W1) {
    int i = blockIdx.x * blockDim.x + threadIdx.x;
    if (i < 512 * 64) {
        int k = i >> 6, n = i & 63;
        g_W1t[n * 512 + k] = W1[i];
    }
}

// ---------------- tf32 mma.sync GEMM1: h1 = x @ W1 ----------------
// CTA tile: M=128, N=64, K chunks of 32. 8 warps: warpM = wid&3 (M32), warpN = wid>>2 (N32).
// Warp tile 32x32 = 2 (M16) x 4 (N8) mma tiles.
#define KC 32
#define ASTRIDE 36

__global__ __launch_bounds__(256) void sgemm1_mma_kernel(const float* __restrict__ A) {
    __shared__ uint32_t As[128 * ASTRIDE];   // [m][k] tf32 bits
    __shared__ uint32_t Bs[64 * ASTRIDE];    // [n][k] tf32 bits
    int t = threadIdx.x;
    int lane = t & 31, wid = t >> 5;
    int g = lane >> 2, tg = lane & 3;        // groupID, threadID_in_group
    int warpM = (wid & 3) * 32;
    int warpN = (wid >> 2) * 32;
    int row0 = blockIdx.x * 128;

    float c[2][4][4];
#pragma unroll
    for (int mi = 0; mi < 2; mi++)
#pragma unroll
        for (int ni = 0; ni < 4; ni++)
#pragma unroll
            for (int q = 0; q < 4; q++) c[mi][ni][q] = 0.f;

    for (int kk = 0; kk < 512; kk += KC) {
        // load A tile: 128 x 32 floats = 1024 float4
#pragma unroll
        for (int i = 0; i < 4; i++) {
            int idx = t + i * 256;        // 0..1023
            int r = idx >> 3, q = idx & 7;
            float4 v = make_float4(0.f, 0.f, 0.f, 0.f);
            if (row0 + r < NN)
                v = *reinterpret_cast<const float4*>(A + (size_t)(row0 + r) * 512 + kk + q * 4);
            uint32_t* p = &As[r * ASTRIDE + q * 4];
            p[0] = f2tf32(v.x); p[1] = f2tf32(v.y); p[2] = f2tf32(v.z); p[3] = f2tf32(v.w);
        }
        // load B tile: 64 x 32 floats = 512 float4
#pragma unroll
        for (int i = 0; i < 2; i++) {
            int idx = t + i * 256;        // 0..511
            int r = idx >> 3, q = idx & 7;
            float4 v = *reinterpret_cast<const float4*>(g_W1t + (size_t)r * 512 + kk + q * 4);
            uint32_t* p = &Bs[r * ASTRIDE + q * 4];
            p[0] = f2tf32(v.x); p[1] = f2tf32(v.y); p[2] = f2tf32(v.z); p[3] = f2tf32(v.w);
        }
        __syncthreads();
#pragma unroll
        for (int k8 = 0; k8 < 4; k8++) {
            int kb = k8 * 8;
            uint32_t a[2][4], b[4][2];
#pragma unroll
            for (int mi = 0; mi < 2; mi++) {
                int m = warpM + mi * 16;
                a[mi][0] = As[(m + g) * ASTRIDE + kb + tg];
                a[mi][1] = As[(m + g + 8) * ASTRIDE + kb + tg];
                a[mi][2] = As[(m + g) * ASTRIDE + kb + tg + 4];
                a[mi][3] = As[(m + g + 8) * ASTRIDE + kb + tg + 4];
            }
#pragma unroll
            for (int ni = 0; ni < 4; ni++) {
                int n = warpN + ni * 8;
                b[ni][0] = Bs[(n + g) * ASTRIDE + kb + tg];
                b[ni][1] = Bs[(n + g) * ASTRIDE + kb + tg + 4];
            }
#pragma unroll
            for (int mi = 0; mi < 2; mi++)
#pragma unroll
                for (int ni = 0; ni < 4; ni++)
                    mma_tf32(c[mi][ni][0], c[mi][ni][1], c[mi][ni][2], c[mi][ni][3],
                             a[mi][0], a[mi][1], a[mi][2], a[mi][3],
                             b[ni][0], b[ni][1]);
        }
        __syncthreads();
    }
    // epilogue: c0=C(g,2t), c1=C(g,2t+1), c2=C(g+8,2t), c3=C(g+8,2t+1)
#pragma unroll
    for (int mi = 0; mi < 2; mi++) {
        int r0 = row0 + warpM + mi * 16 + g;
        int r1 = r0 + 8;
#pragma unroll
        for (int ni = 0; ni < 4; ni++) {
            int col = warpN + ni * 8 + tg * 2;
            if (r0 < NN)
                *reinterpret_cast<float2*>(g_h1 + (size_t)r0 * 64 + col) =
                    make_float2(c[mi][ni][0], c[mi][ni][1]);
            if (r1 < NN)
                *reinterpret_cast<float2*>(g_h1 + (size_t)r1 * 64 + col) =
                    make_float2(c[mi][ni][2], c[mi][ni][3]);
        }
    }
}

// ---------------- attention logits layer 1 ----------------
__global__ void alpha1_kernel(const float* __restrict__ a_src,
                              const float* __restrict__ a_dst) {
    int i = blockIdx.x * blockDim.x + threadIdx.x;
    if (i >= NN * 8) return;
    int n = i >> 3, h = i & 7;
    const float* hp = g_h1 + (size_t)n * 64 + h * 8;
    const float* asp = a_src + h * 8;
    const float* adp = a_dst + h * 8;
    float s = 0.f, d = 0.f;
#pragma unroll
    for (int c = 0; c < 8; c++) {
        float v = hp[c];
        s += v * asp[c];
        d += v * adp[c];
    }
    g_as1[i] = s;
    g_ad1[i] = d;
}

// ---------------- layer-1 gather: one warp per dst node (fused finalize) ----
__global__ __launch_bounds__(256) void gather1_kernel(const float* __restrict__ b1) {
    int warp_id = (blockIdx.x * blockDim.x + threadIdx.x) >> 5;
    if (warp_id >= NN) return;
    int l = threadIdx.x & 31;
    int n = warp_id;
    int h = l >> 2;
    float ad_h = g_ad1[n * 8 + h];
    int st = g_start[n];
    int deg = g_cnt[n];
    float acc0 = 0.f, acc1 = 0.f, den = 0.f;
    for (int i = 0; i < deg; i++) {
        int s = g_csr[st + i];
        float w = lrexp(g_as1[s * 8 + h] + ad_h);
        float2 hv = *reinterpret_cast<const float2*>(g_h1 + (size_t)s * 64 + 2 * l);
        acc0 += w * hv.x;
        acc1 += w * hv.y;
        if ((l & 3) == 0) den += w;
    }
    float wself = lrexp(g_as1[n * 8 + h] + ad_h);
    float2 hs = *reinterpret_cast<const float2*>(g_h1 + (size_t)n * 64 + 2 * l);
    acc0 += wself * hs.x;
    acc1 += wself * hs.y;
    if ((l & 3) == 0) den += wself;
    float den_all = __shfl_sync(0xffffffffu, den, l & ~3);
    float inv = 1.0f / (den_all + 1e-16f);
    float2 bv = *reinterpret_cast<const float2*>(b1 + 2 * l);
    float2 o = make_float2(acc0 * inv + bv.x, acc1 * inv + bv.y);
    *reinterpret_cast<float2*>(g_out1 + (size_t)n * 64 + 2 * l) = o;
}

// ---------------- layer-2 transform ----------------
__global__ __launch_bounds__(128) void gemm2_kernel(const float* __restrict__ W2,
                                                    const float* __restrict__ a_src,
                                                    const float* __restrict__ a_dst) {
    __shared__ float sW[448];
    __shared__ float sa[7], sd[7];
    int t = threadIdx.x;
    for (int j = t; j < 448; j += blockDim.x) sW[j] = W2[j];
    if (t < 7) { sa[t] = a_src[t]; sd[t] = a_dst[t]; }
    __syncthreads();
    int n = blockIdx.x * blockDim.x + t;
    if (n >= NN) return;
    float v[64];
    const float4* row = (const float4*)g_out1 + (size_t)n * 16;
#pragma unroll
    for (int q = 0; q < 16; q++) {
        float4 x = row[q];
        v[4 * q] = x.x; v[4 * q + 1] = x.y; v[4 * q + 2] = x.z; v[4 * q + 3] = x.w;
    }
    float h[7] = {0.f, 0.f, 0.f, 0.f, 0.f, 0.f, 0.f};
#pragma unroll 8
    for (int k = 0; k < 64; k++) {
        float vk = v[k];
#pragma unroll
        for (int c = 0; c < 7; c++) h[c] += vk * sW[k * 7 + c];
    }
    float s = 0.f, d = 0.f;
#pragma unroll
    for (int c = 0; c < 7; c++) { s += h[c] * sa[c]; d += h[c] * sd[c]; }
    float* hp = g_h2 + (size_t)n * 8;
#pragma unroll
    for (int c = 0; c < 7; c++) hp[c] = h[c];
    hp[7] = 1.0f;
    g_as2[n] = s;
    g_ad2[n] = d;
}

// ---------------- layer-2 gather (fused finalize + log_softmax) ------------
__global__ __launch_bounds__(256) void gather2_kernel(const float* __restrict__ b2,
                                                      float* __restrict__ out) {
    int gid = blockIdx.x * blockDim.x + threadIdx.x;
    int n = gid >> 3;
    if (n >= NN) return;
    int c = gid & 7;
    float ad = g_ad2[n];
    int st = g_start[n];
    int deg = g_cnt[n];
    float acc = 0.f;
    for (int i = 0; i < deg; i++) {
        int s = g_csr[st + i];
        float w = lrexp(g_as2[s] + ad);
        acc += w * g_h2[(size_t)s * 8 + c];
    }
    float wself = lrexp(g_as2[n] + ad);
    acc += wself * g_h2[(size_t)n * 8 + c];
    float den = __shfl_sync(0xffffffffu, acc, (threadIdx.x & ~7) | 7);
    float inv = 1.0f / (den + 1e-16f);
    float o = (c < 7) ? (acc * inv + b2[c]) : -1e30f;
    float m = o;
#pragma unroll
    for (int off = 1; off < 8; off <<= 1)
        m = fmaxf(m, __shfl_xor_sync(0xffffffffu, m, off));
    float ex = (c < 7) ? __expf(o - m) : 0.f;
    float sum = ex;
#pragma unroll
    for (int off = 1; off < 8; off <<= 1)
        sum += __shfl_xor_sync(0xffffffffu, sum, off);
    float lse = m + logf(sum);
    if (c < 7) out[(size_t)n * 7 + c] = o - lse;
}

// ---------------- launcher ----------------
extern "C" void kernel_launch(void* const* d_in, const int* in_sizes, int n_in,
                              void* d_out, int out_size) {
    const float* x    = (const float*)d_in[0];
    const int*   ei   = (const int*)d_in[1];
    const float* W1   = (const float*)d_in[2];
    const float* as1  = (const float*)d_in[3];
    const float* ad1  = (const float*)d_in[4];
    const float* b1   = (const float*)d_in[5];
    const float* W2   = (const float*)d_in[6];
    const float* as2  = (const float*)d_in[7];
    const float* ad2  = (const float*)d_in[8];
    const float* b2   = (const float*)d_in[9];
    float* out = (float*)d_out;
    int E = in_sizes[1] / 2;
    const int* src = ei;
    const int* dst = ei + E;

    zero_cnt_kernel<<<(NN + 255) / 256, 256>>>();
    hist_kernel<<<(E + 255) / 256, 256>>>(dst, E);
    scan1_kernel<<<NBLK, 256>>>();
    scan2_kernel<<<1, 128>>>();
    scan3_kernel<<<(NN + 255) / 256, 256>>>();
    scatter_kernel<<<(E + 255) / 256, 256>>>(src, dst, E);

    transposeW1_kernel<<<(512 * 64 + 255) / 256, 256>>>(W1);
    sgemm1_mma_kernel<<<(NN + 127) / 128, 256>>>(x);
    alpha1_kernel<<<(NN * 8 + 255) / 256, 256>>>(as1, ad1);
    gather1_kernel<<<(NN * 32 + 255) / 256, 256>>>(b1);
    gemm2_kernel<<<(NN + 127) / 128, 128>>>(W2, as2, ad2);
    gather2_kernel<<<(NN * 8 + 255) / 256, 256>>>(b2, out);
}

// round 7
// speedup vs baseline: 2.4664x; 1.0530x over previous
#include <cuda_runtime.h>
#include <cuda_bf16.h>
#include <cstdint>

#define NN 100000
#define EE_MAX 3200000
#define SCAN_BLK 1024
#define NBLK ((NN + SCAN_BLK - 1) / SCAN_BLK)   // 98

// ---------------- device scratch (static, allocation-free) ----------------
__device__ float g_h1[NN * 64];              // layer1 features fp32 (for logits)
__device__ __nv_bfloat16 g_h1b[NN * 64];     // layer1 features bf16 (for gather)
__device__ float g_as1[NN * 8];
__device__ float g_ad1[NN * 8];
__device__ float g_out1[NN * 64];
__device__ float g_h2[NN * 8];               // layer2 features [N,7] + ones slot
__device__ float g_as2[NN];
__device__ float g_ad2[NN];
__device__ float g_W1t[64 * 512];            // W1 transposed [N=64][K=512]

__device__ int g_cnt[NN];
__device__ int g_start[NN];
__device__ int g_cursor[NN];
__device__ int g_bsum[NBLK];
__device__ int g_csr[EE_MAX];

__device__ __forceinline__ float lrexp(float x) {
    x = x > 0.0f ? x : 0.2f * x;
    return __expf(x);
}

__device__ __forceinline__ uint32_t smem_u32(const void* p) {
    uint32_t a;
    asm("{ .reg .u64 t; cvta.to.shared.u64 t, %1; cvt.u32.u64 %0, t; }" : "=r"(a) : "l"(p));
    return a;
}
__device__ __forceinline__ void cpa16(uint32_t saddr, const void* g, int src_sz) {
    asm volatile("cp.async.cg.shared.global [%0], [%1], 16, %2;"
                 :: "r"(saddr), "l"(g), "r"(src_sz) : "memory");
}
#define CPA_COMMIT() asm volatile("cp.async.commit_group;" ::: "memory")
#define CPA_WAIT(n)  asm volatile("cp.async.wait_group %0;" :: "n"(n) : "memory")

__device__ __forceinline__ void mma_tf32(float& c0, float& c1, float& c2, float& c3,
                                         uint32_t a0, uint32_t a1, uint32_t a2, uint32_t a3,
                                         uint32_t b0, uint32_t b1) {
    asm volatile(
        "mma.sync.aligned.m16n8k8.row.col.f32.tf32.tf32.f32 "
        "{%0,%1,%2,%3}, {%4,%5,%6,%7}, {%8,%9}, {%0,%1,%2,%3};"
        : "+f"(c0), "+f"(c1), "+f"(c2), "+f"(c3)
        : "r"(a0), "r"(a1), "r"(a2), "r"(a3), "r"(b0), "r"(b1));
}

// ---------------- CSR build ----------------
__global__ void zero_cnt_kernel() {
    int i = blockIdx.x * blockDim.x + threadIdx.x;
    if (i < NN) g_cnt[i] = 0;
}

__global__ void hist_kernel(const int* __restrict__ dst, int E) {
    int e = blockIdx.x * blockDim.x + threadIdx.x;
    if (e < E) atomicAdd(&g_cnt[dst[e]], 1);
}

__global__ __launch_bounds__(256) void scan1_kernel() {
    __shared__ int warp_tot[8];
    int b = blockIdx.x, t = threadIdx.x;
    int base = b * SCAN_BLK + t * 4;
    int v[4];
#pragma unroll
    for (int k = 0; k < 4; k++) v[k] = (base + k < NN) ? g_cnt[base + k] : 0;
    int tsum = v[0] + v[1] + v[2] + v[3];
    int lane = t & 31, wid = t >> 5;
    int inc = tsum;
#pragma unroll
    for (int off = 1; off < 32; off <<= 1) {
        int n = __shfl_up_sync(0xffffffffu, inc, off);
        if (lane >= off) inc += n;
    }
    if (lane == 31) warp_tot[wid] = inc;
    __syncthreads();
    if (wid == 0) {
        int w = (lane < 8) ? warp_tot[lane] : 0;
#pragma unroll
        for (int off = 1; off < 8; off <<= 1) {
            int n = __shfl_up_sync(0xffffffffu, w, off);
            if (lane >= off) w += n;
        }
        if (lane < 8) warp_tot[lane] = w;
    }
    __syncthreads();
    int excl = inc - tsum + (wid > 0 ? warp_tot[wid - 1] : 0);
#pragma unroll
    for (int k = 0; k < 4; k++) {
        if (base + k < NN) g_start[base + k] = excl;
        excl += v[k];
    }
    if (t == 255) g_bsum[b] = excl;
}

__global__ void scan2_kernel() {
    __shared__ int s[128];
    int t = threadIdx.x;
    int v = (t < NBLK) ? g_bsum[t] : 0;
    s[t] = v;
    __syncthreads();
#pragma unroll
    for (int off = 1; off < 128; off <<= 1) {
        int x = (t >= off) ? s[t - off] : 0;
        __syncthreads();
        s[t] += x;
        __syncthreads();
    }
    if (t < NBLK) g_bsum[t] = s[t] - v;
}

__global__ void scan3_kernel() {
    int i = blockIdx.x * blockDim.x + threadIdx.x;
    if (i < NN) {
        int s = g_start[i] + g_bsum[i / SCAN_BLK];
        g_start[i] = s;
        g_cursor[i] = s;
    }
}

__global__ void scatter_kernel(const int* __restrict__ src,
                               const int* __restrict__ dst, int E) {
    int e = blockIdx.x * blockDim.x + threadIdx.x;
    if (e < E) {
        int pos = atomicAdd(&g_cursor[dst[e]], 1);
        g_csr[pos] = src[e];
    }
}

// ---------------- W1 transpose ----------------
__global__ void transposeW1_kernel(const float* __restrict__ W1) {
    int i = blockIdx.x * blockDim.x + threadIdx.x;
    if (i < 512 * 64) {
        int k = i >> 6, n = i & 63;
        g_W1t[n * 512 + k] = W1[i];
    }
}

// ---------------- tf32 mma.sync GEMM1 (cp.async double-buffered) ----------
#define KC 32
#define ASTRIDE 36

__global__ __launch_bounds__(256) void sgemm1_mma_kernel(const float* __restrict__ A) {
    __shared__ uint32_t As[2][128 * ASTRIDE];
    __shared__ uint32_t Bs[2][64 * ASTRIDE];
    int t = threadIdx.x;
    int lane = t & 31, wid = t >> 5;
    int g = lane >> 2, tg = lane & 3;
    int warpM = (wid & 3) * 32;
    int warpN = (wid >> 2) * 32;
    int row0 = blockIdx.x * 128;

    float c[2][4][4];
#pragma unroll
    for (int mi = 0; mi < 2; mi++)
#pragma unroll
        for (int ni = 0; ni < 4; ni++)
#pragma unroll
            for (int q = 0; q < 4; q++) c[mi][ni][q] = 0.f;

    // prologue: async-load chunk 0 into buf 0
#pragma unroll
    for (int i = 0; i < 4; i++) {
        int idx = t + i * 256;
        int r = idx >> 3, q = idx & 7;
        int row = row0 + r;
        int rc = row < NN ? row : NN - 1;
        int sz = row < NN ? 16 : 0;
        cpa16(smem_u32(&As[0][r * ASTRIDE + q * 4]),
              A + (size_t)rc * 512 + q * 4, sz);
    }
#pragma unroll
    for (int i = 0; i < 2; i++) {
        int idx = t + i * 256;
        int r = idx >> 3, q = idx & 7;
        cpa16(smem_u32(&Bs[0][r * ASTRIDE + q * 4]),
              g_W1t + (size_t)r * 512 + q * 4, 16);
    }
    CPA_COMMIT();

    for (int cidx = 0; cidx < 16; cidx++) {
        int b = cidx & 1;
        if (cidx < 15) {
            int kk = (cidx + 1) * KC;
            int bn = b ^ 1;
#pragma unroll
            for (int i = 0; i < 4; i++) {
                int idx = t + i * 256;
                int r = idx >> 3, q = idx & 7;
                int row = row0 + r;
                int rc = row < NN ? row : NN - 1;
                int sz = row < NN ? 16 : 0;
                cpa16(smem_u32(&As[bn][r * ASTRIDE + q * 4]),
                      A + (size_t)rc * 512 + kk + q * 4, sz);
            }
#pragma unroll
            for (int i = 0; i < 2; i++) {
                int idx = t + i * 256;
                int r = idx >> 3, q = idx & 7;
                cpa16(smem_u32(&Bs[bn][r * ASTRIDE + q * 4]),
                      g_W1t + (size_t)r * 512 + kk + q * 4, 16);
            }
            CPA_COMMIT();
            CPA_WAIT(1);
        } else {
            CPA_WAIT(0);
        }
        __syncthreads();
#pragma unroll
        for (int k8 = 0; k8 < 4; k8++) {
            int kb = k8 * 8;
            uint32_t a[2][4], bb[4][2];
#pragma unroll
            for (int mi = 0; mi < 2; mi++) {
                int m = warpM + mi * 16;
                a[mi][0] = As[b][(m + g) * ASTRIDE + kb + tg];
                a[mi][1] = As[b][(m + g + 8) * ASTRIDE + kb + tg];
                a[mi][2] = As[b][(m + g) * ASTRIDE + kb + tg + 4];
                a[mi][3] = As[b][(m + g + 8) * ASTRIDE + kb + tg + 4];
            }
#pragma unroll
            for (int ni = 0; ni < 4; ni++) {
                int n = warpN + ni * 8;
                bb[ni][0] = Bs[b][(n + g) * ASTRIDE + kb + tg];
                bb[ni][1] = Bs[b][(n + g) * ASTRIDE + kb + tg + 4];
            }
#pragma unroll
            for (int mi = 0; mi < 2; mi++)
#pragma unroll
                for (int ni = 0; ni < 4; ni++)
                    mma_tf32(c[mi][ni][0], c[mi][ni][1], c[mi][ni][2], c[mi][ni][3],
                             a[mi][0], a[mi][1], a[mi][2], a[mi][3],
                             bb[ni][0], bb[ni][1]);
        }
        __syncthreads();
    }
    // epilogue: fp32 + bf16 writes
#pragma unroll
    for (int mi = 0; mi < 2; mi++) {
        int r0 = row0 + warpM + mi * 16 + g;
        int r1 = r0 + 8;
#pragma unroll
        for (int ni = 0; ni < 4; ni++) {
            int col = warpN + ni * 8 + tg * 2;
            if (r0 < NN) {
                *reinterpret_cast<float2*>(g_h1 + (size_t)r0 * 64 + col) =
                    make_float2(c[mi][ni][0], c[mi][ni][1]);
                reinterpret_cast<__nv_bfloat162*>(g_h1b)[(size_t)r0 * 32 + (col >> 1)] =
                    __floats2bfloat162_rn(c[mi][ni][0], c[mi][ni][1]);
            }
            if (r1 < NN) {
                *reinterpret_cast<float2*>(g_h1 + (size_t)r1 * 64 + col) =
                    make_float2(c[mi][ni][2], c[mi][ni][3]);
                reinterpret_cast<__nv_bfloat162*>(g_h1b)[(size_t)r1 * 32 + (col >> 1)] =
                    __floats2bfloat162_rn(c[mi][ni][2], c[mi][ni][3]);
            }
        }
    }
}

// ---------------- attention logits layer 1 (fp32 h1) ----------------
__global__ void alpha1_kernel(const float* __restrict__ a_src,
                              const float* __restrict__ a_dst) {
    int i = blockIdx.x * blockDim.x + threadIdx.x;
    if (i >= NN * 8) return;
    int n = i >> 3, h = i & 7;
    const float* hp = g_h1 + (size_t)n * 64 + h * 8;
    const float* asp = a_src + h * 8;
    const float* adp = a_dst + h * 8;
    float s = 0.f, d = 0.f;
#pragma unroll
    for (int c = 0; c < 8; c++) {
        float v = hp[c];
        s += v * asp[c];
        d += v * adp[c];
    }
    g_as1[i] = s;
    g_ad1[i] = d;
}

// ---------------- layer-1 gather: warp per dst, bf16 features --------------
__global__ __launch_bounds__(256) void gather1_kernel(const float* __restrict__ b1) {
    int warp_id = (blockIdx.x * blockDim.x + threadIdx.x) >> 5;
    if (warp_id >= NN) return;
    int l = threadIdx.x & 31;
    int n = warp_id;
    int h = l >> 2;
    float ad_h = g_ad1[n * 8 + h];
    int st = g_start[n];
    int deg = g_cnt[n];
    const __nv_bfloat162* hb = reinterpret_cast<const __nv_bfloat162*>(g_h1b);
    float acc0 = 0.f, acc1 = 0.f, den = 0.f;
    int i = 0;
    for (; i + 2 <= deg; i += 2) {
        int s0 = g_csr[st + i];
        int s1 = g_csr[st + i + 1];
        float w0 = lrexp(g_as1[s0 * 8 + h] + ad_h);
        float w1 = lrexp(g_as1[s1 * 8 + h] + ad_h);
        float2 f0 = __bfloat1622float2(hb[(size_t)s0 * 32 + l]);
        float2 f1 = __bfloat1622float2(hb[(size_t)s1 * 32 + l]);
        acc0 += w0 * f0.x + w1 * f1.x;
        acc1 += w0 * f0.y + w1 * f1.y;
        if ((l & 3) == 0) den += w0 + w1;
    }
    if (i < deg) {
        int s0 = g_csr[st + i];
        float w0 = lrexp(g_as1[s0 * 8 + h] + ad_h);
        float2 f0 = __bfloat1622float2(hb[(size_t)s0 * 32 + l]);
        acc0 += w0 * f0.x;
        acc1 += w0 * f0.y;
        if ((l & 3) == 0) den += w0;
    }
    // self loop
    float wself = lrexp(g_as1[n * 8 + h] + ad_h);
    float2 fs = __bfloat1622float2(hb[(size_t)n * 32 + l]);
    acc0 += wself * fs.x;
    acc1 += wself * fs.y;
    if ((l & 3) == 0) den += wself;
    float den_all = __shfl_sync(0xffffffffu, den, l & ~3);
    float inv = 1.0f / (den_all + 1e-16f);
    float2 bv = *reinterpret_cast<const float2*>(b1 + 2 * l);
    float2 o = make_float2(acc0 * inv + bv.x, acc1 * inv + bv.y);
    *reinterpret_cast<float2*>(g_out1 + (size_t)n * 64 + 2 * l) = o;
}

// ---------------- layer-2 transform ----------------
__global__ __launch_bounds__(128) void gemm2_kernel(const float* __restrict__ W2,
                                                    const float* __restrict__ a_src,
                                                    const float* __restrict__ a_dst) {
    __shared__ float sW[448];
    __shared__ float sa[7], sd[7];
    int t = threadIdx.x;
    for (int j = t; j < 448; j += blockDim.x) sW[j] = W2[j];
    if (t < 7) { sa[t] = a_src[t]; sd[t] = a_dst[t]; }
    __syncthreads();
    int n = blockIdx.x * blockDim.x + t;
    if (n >= NN) return;
    float v[64];
    const float4* row = (const float4*)g_out1 + (size_t)n * 16;
#pragma unroll
    for (int q = 0; q < 16; q++) {
        float4 x = row[q];
        v[4 * q] = x.x; v[4 * q + 1] = x.y; v[4 * q + 2] = x.z; v[4 * q + 3] = x.w;
    }
    float h[7] = {0.f, 0.f, 0.f, 0.f, 0.f, 0.f, 0.f};
#pragma unroll 8
    for (int k = 0; k < 64; k++) {
        float vk = v[k];
#pragma unroll
        for (int c = 0; c < 7; c++) h[c] += vk * sW[k * 7 + c];
    }
    float s = 0.f, d = 0.f;
#pragma unroll
    for (int c = 0; c < 7; c++) { s += h[c] * sa[c]; d += h[c] * sd[c]; }
    float* hp = g_h2 + (size_t)n * 8;
#pragma unroll
    for (int c = 0; c < 7; c++) hp[c] = h[c];
    hp[7] = 1.0f;
    g_as2[n] = s;
    g_ad2[n] = d;
}

// ---------------- layer-2 gather (fused finalize + log_softmax) ------------
__global__ __launch_bounds__(256) void gather2_kernel(const float* __restrict__ b2,
                                                      float* __restrict__ out) {
    int gid = blockIdx.x * blockDim.x + threadIdx.x;
    int n = gid >> 3;
    if (n >= NN) return;
    int c = gid & 7;
    float ad = g_ad2[n];
    int st = g_start[n];
    int deg = g_cnt[n];
    float acc = 0.f;
    int i = 0;
    for (; i + 2 <= deg; i += 2) {
        int s0 = g_csr[st + i];
        int s1 = g_csr[st + i + 1];
        float w0 = lrexp(g_as2[s0] + ad);
        float w1 = lrexp(g_as2[s1] + ad);
        acc += w0 * g_h2[(size_t)s0 * 8 + c] + w1 * g_h2[(size_t)s1 * 8 + c];
    }
    if (i < deg) {
        int s0 = g_csr[st + i];
        float w0 = lrexp(g_as2[s0] + ad);
        acc += w0 * g_h2[(size_t)s0 * 8 + c];
    }
    float wself = lrexp(g_as2[n] + ad);
    acc += wself * g_h2[(size_t)n * 8 + c];
    float den = __shfl_sync(0xffffffffu, acc, (threadIdx.x & ~7) | 7);
    float inv = 1.0f / (den + 1e-16f);
    float o = (c < 7) ? (acc * inv + b2[c]) : -1e30f;
    float m = o;
#pragma unroll
    for (int off = 1; off < 8; off <<= 1)
        m = fmaxf(m, __shfl_xor_sync(0xffffffffu, m, off));
    float ex = (c < 7) ? __expf(o - m) : 0.f;
    float sum = ex;
#pragma unroll
    for (int off = 1; off < 8; off <<= 1)
        sum += __shfl_xor_sync(0xffffffffu, sum, off);
    float lse = m + logf(sum);
    if (c < 7) out[(size_t)n * 7 + c] = o - lse;
}

// ---------------- launcher ----------------
extern "C" void kernel_launch(void* const* d_in, const int* in_sizes, int n_in,
                              void* d_out, int out_size) {
    const float* x    = (const float*)d_in[0];
    const int*   ei   = (const int*)d_in[1];
    const float* W1   = (const float*)d_in[2];
    const float* as1  = (const float*)d_in[3];
    const float* ad1  = (const float*)d_in[4];
    const float* b1   = (const float*)d_in[5];
    const float* W2   = (const float*)d_in[6];
    const float* as2  = (const float*)d_in[7];
    const float* ad2  = (const float*)d_in[8];
    const float* b2   = (const float*)d_in[9];
    float* out = (float*)d_out;
    int E = in_sizes[1] / 2;
    const int* src = ei;
    const int* dst = ei + E;

    zero_cnt_kernel<<<(NN + 255) / 256, 256>>>();
    hist_kernel<<<(E + 255) / 256, 256>>>(dst, E);
    scan1_kernel<<<NBLK, 256>>>();
    scan2_kernel<<<1, 128>>>();
    scan3_kernel<<<(NN + 255) / 256, 256>>>();
    scatter_kernel<<<(E + 255) / 256, 256>>>(src, dst, E);

    transposeW1_kernel<<<(512 * 64 + 255) / 256, 256>>>(W1);
    sgemm1_mma_kernel<<<(NN + 127) / 128, 256>>>(x);
    alpha1_kernel<<<(NN * 8 + 255) / 256, 256>>>(as1, ad1);
    gather1_kernel<<<(NN * 32 + 255) / 256, 256>>>(b1);
    gemm2_kernel<<<(NN + 127) / 128, 128>>>(W2, as2, ad2);
    gather2_kernel<<<(NN * 8 + 255) / 256, 256>>>(b2, out);
}

// round 9
// speedup vs baseline: 3.0972x; 1.2558x over previous
#include <cuda_runtime.h>
#include <cuda_bf16.h>
#include <cstdint>

#define NN 100000
#define EE_MAX 3200000
#define SCAN_BLK 1024
#define NBLK ((NN + SCAN_BLK - 1) / SCAN_BLK)   // 98

// ---------------- device scratch (static, allocation-free) ----------------
__device__ __nv_bfloat16 g_h1b[NN * 64];     // layer1 features bf16
__device__ float g_as1[NN * 8];
__device__ float g_ad1[NN * 8];
__device__ float g_out1[NN * 64];
__device__ float g_h2[NN * 8];               // layer2 features [N,7] + ones slot
__device__ float g_as2[NN];
__device__ float g_ad2[NN];
__device__ float g_W1t[64 * 512];            // W1 transposed [N=64][K=512]

__device__ int g_cnt[NN];
__device__ int g_start[NN];
__device__ int g_bsum[NBLK];
__device__ int g_rank[EE_MAX];               // edge rank within its dst
__device__ int g_csr[EE_MAX];                // src ids sorted by dst

__device__ __forceinline__ float lrexp(float x) {
    x = x > 0.0f ? x : 0.2f * x;
    return __expf(x);
}

__device__ __forceinline__ uint32_t smem_u32(const void* p) {
    uint32_t a;
    asm("{ .reg .u64 t; cvta.to.shared.u64 t, %1; cvt.u32.u64 %0, t; }" : "=r"(a) : "l"(p));
    return a;
}
__device__ __forceinline__ void cpa16(uint32_t saddr, const void* g, int src_sz) {
    asm volatile("cp.async.cg.shared.global [%0], [%1], 16, %2;"
                 :: "r"(saddr), "l"(g), "r"(src_sz) : "memory");
}
#define CPA_COMMIT() asm volatile("cp.async.commit_group;" ::: "memory")
#define CPA_WAIT(n)  asm volatile("cp.async.wait_group %0;" :: "n"(n) : "memory")

__device__ __forceinline__ void mma_tf32(float& c0, float& c1, float& c2, float& c3,
                                         uint32_t a0, uint32_t a1, uint32_t a2, uint32_t a3,
                                         uint32_t b0, uint32_t b1) {
    asm volatile(
        "mma.sync.aligned.m16n8k8.row.col.f32.tf32.tf32.f32 "
        "{%0,%1,%2,%3}, {%4,%5,%6,%7}, {%8,%9}, {%0,%1,%2,%3};"
        : "+f"(c0), "+f"(c1), "+f"(c2), "+f"(c3)
        : "r"(a0), "r"(a1), "r"(a2), "r"(a3), "r"(b0), "r"(b1));
}

// ---------------- prep: zero counts + transpose W1 (fused) ----------------
__global__ void prep_kernel(const float* __restrict__ W1) {
    int i = blockIdx.x * blockDim.x + threadIdx.x;
    if (i < NN) g_cnt[i] = 0;
    if (i < 512 * 64) {
        int k = i >> 6, n = i & 63;
        g_W1t[n * 512 + k] = W1[i];
    }
}

// ---------------- hist + rank ----------------
__global__ void hist_kernel(const int* __restrict__ dst, int E) {
    int e = blockIdx.x * blockDim.x + threadIdx.x;
    if (e < E) g_rank[e] = atomicAdd(&g_cnt[dst[e]], 1);
}

__global__ __launch_bounds__(256) void scan1_kernel() {
    __shared__ int warp_tot[8];
    int b = blockIdx.x, t = threadIdx.x;
    int base = b * SCAN_BLK + t * 4;
    int v[4];
#pragma unroll
    for (int k = 0; k < 4; k++) v[k] = (base + k < NN) ? g_cnt[base + k] : 0;
    int tsum = v[0] + v[1] + v[2] + v[3];
    int lane = t & 31, wid = t >> 5;
    int inc = tsum;
#pragma unroll
    for (int off = 1; off < 32; off <<= 1) {
        int n = __shfl_up_sync(0xffffffffu, inc, off);
        if (lane >= off) inc += n;
    }
    if (lane == 31) warp_tot[wid] = inc;
    __syncthreads();
    if (wid == 0) {
        int w = (lane < 8) ? warp_tot[lane] : 0;
#pragma unroll
        for (int off = 1; off < 8; off <<= 1) {
            int n = __shfl_up_sync(0xffffffffu, w, off);
            if (lane >= off) w += n;
        }
        if (lane < 8) warp_tot[lane] = w;
    }
    __syncthreads();
    int excl = inc - tsum + (wid > 0 ? warp_tot[wid - 1] : 0);
#pragma unroll
    for (int k = 0; k < 4; k++) {
        if (base + k < NN) g_start[base + k] = excl;
        excl += v[k];
    }
    if (t == 255) g_bsum[b] = excl;
}

// scan3 with fused cross-block prefix (each block prefixes the <=98 bsums)
__global__ __launch_bounds__(256) void scan3_kernel() {
    __shared__ int pre[2];
    int b = blockIdx.x, t = threadIdx.x;
    int i = b * 256 + t;
    int seg0 = (b * 256) >> 10;
    int seg1 = (b * 256 + 255) >> 10;
    if (t == 0) {
        int a = 0;
        for (int j = 0; j < seg0; j++) a += g_bsum[j];
        pre[0] = a;
        pre[1] = (seg1 == seg0) ? a : a + g_bsum[seg0];
    }
    __syncthreads();
    if (i < NN)
        g_start[i] += ((i >> 10) == seg0) ? pre[0] : pre[1];
}

// scatter without atomics (uses precomputed rank)
__global__ void scatter_kernel(const int* __restrict__ src,
                               const int* __restrict__ dst, int E) {
    int e = blockIdx.x * blockDim.x + threadIdx.x;
    if (e < E)
        g_csr[g_start[dst[e]] + g_rank[e]] = src[e];
}

// ---------------- tf32 mma.sync GEMM1 (cp.async double-buffered) ----------
#define KC 32
#define ASTRIDE 36

__global__ __launch_bounds__(256) void sgemm1_mma_kernel(const float* __restrict__ A) {
    __shared__ uint32_t As[2][128 * ASTRIDE];
    __shared__ uint32_t Bs[2][64 * ASTRIDE];
    int t = threadIdx.x;
    int lane = t & 31, wid = t >> 5;
    int g = lane >> 2, tg = lane & 3;
    int warpM = (wid & 3) * 32;
    int warpN = (wid >> 2) * 32;
    int row0 = blockIdx.x * 128;

    float c[2][4][4];
#pragma unroll
    for (int mi = 0; mi < 2; mi++)
#pragma unroll
        for (int ni = 0; ni < 4; ni++)
#pragma unroll
            for (int q = 0; q < 4; q++) c[mi][ni][q] = 0.f;

#pragma unroll
    for (int i = 0; i < 4; i++) {
        int idx = t + i * 256;
        int r = idx >> 3, q = idx & 7;
        int row = row0 + r;
        int rc = row < NN ? row : NN - 1;
        int sz = row < NN ? 16 : 0;
        cpa16(smem_u32(&As[0][r * ASTRIDE + q * 4]),
              A + (size_t)rc * 512 + q * 4, sz);
    }
#pragma unroll
    for (int i = 0; i < 2; i++) {
        int idx = t + i * 256;
        int r = idx >> 3, q = idx & 7;
        cpa16(smem_u32(&Bs[0][r * ASTRIDE + q * 4]),
              g_W1t + (size_t)r * 512 + q * 4, 16);
    }
    CPA_COMMIT();

    for (int cidx = 0; cidx < 16; cidx++) {
        int b = cidx & 1;
        if (cidx < 15) {
            int kk = (cidx + 1) * KC;
            int bn = b ^ 1;
#pragma unroll
            for (int i = 0; i < 4; i++) {
                int idx = t + i * 256;
                int r = idx >> 3, q = idx & 7;
                int row = row0 + r;
                int rc = row < NN ? row : NN - 1;
                int sz = row < NN ? 16 : 0;
                cpa16(smem_u32(&As[bn][r * ASTRIDE + q * 4]),
                      A + (size_t)rc * 512 + kk + q * 4, sz);
            }
#pragma unroll
            for (int i = 0; i < 2; i++) {
                int idx = t + i * 256;
                int r = idx >> 3, q = idx & 7;
                cpa16(smem_u32(&Bs[bn][r * ASTRIDE + q * 4]),
                      g_W1t + (size_t)r * 512 + kk + q * 4, 16);
            }
            CPA_COMMIT();
            CPA_WAIT(1);
        } else {
            CPA_WAIT(0);
        }
        __syncthreads();
#pragma unroll
        for (int k8 = 0; k8 < 4; k8++) {
            int kb = k8 * 8;
            uint32_t a[2][4], bb[4][2];
#pragma unroll
            for (int mi = 0; mi < 2; mi++) {
                int m = warpM + mi * 16;
                a[mi][0] = As[b][(m + g) * ASTRIDE + kb + tg];
                a[mi][1] = As[b][(m + g + 8) * ASTRIDE + kb + tg];
                a[mi][2] = As[b][(m + g) * ASTRIDE + kb + tg + 4];
                a[mi][3] = As[b][(m + g + 8) * ASTRIDE + kb + tg + 4];
            }
#pragma unroll
            for (int ni = 0; ni < 4; ni++) {
                int n = warpN + ni * 8;
                bb[ni][0] = Bs[b][(n + g) * ASTRIDE + kb + tg];
                bb[ni][1] = Bs[b][(n + g) * ASTRIDE + kb + tg + 4];
            }
#pragma unroll
            for (int mi = 0; mi < 2; mi++)
#pragma unroll
                for (int ni = 0; ni < 4; ni++)
                    mma_tf32(c[mi][ni][0], c[mi][ni][1], c[mi][ni][2], c[mi][ni][3],
                             a[mi][0], a[mi][1], a[mi][2], a[mi][3],
                             bb[ni][0], bb[ni][1]);
        }
        __syncthreads();
    }
    // epilogue: bf16 only
#pragma unroll
    for (int mi = 0; mi < 2; mi++) {
        int r0 = row0 + warpM + mi * 16 + g;
        int r1 = r0 + 8;
#pragma unroll
        for (int ni = 0; ni < 4; ni++) {
            int col = warpN + ni * 8 + tg * 2;
            if (r0 < NN)
                reinterpret_cast<__nv_bfloat162*>(g_h1b)[(size_t)r0 * 32 + (col >> 1)] =
                    __floats2bfloat162_rn(c[mi][ni][0], c[mi][ni][1]);
            if (r1 < NN)
                reinterpret_cast<__nv_bfloat162*>(g_h1b)[(size_t)r1 * 32 + (col >> 1)] =
                    __floats2bfloat162_rn(c[mi][ni][2], c[mi][ni][3]);
        }
    }
}

// ---------------- attention logits layer 1 (bf16 h) ----------------
__global__ void alpha1_kernel(const float* __restrict__ a_src,
                              const float* __restrict__ a_dst) {
    int i = blockIdx.x * blockDim.x + threadIdx.x;
    if (i >= NN * 8) return;
    int n = i >> 3, h = i & 7;
    uint4 raw = *reinterpret_cast<const uint4*>(g_h1b + (size_t)n * 64 + h * 8);
    const __nv_bfloat162* hp = reinterpret_cast<const __nv_bfloat162*>(&raw);
    const float* asp = a_src + h * 8;
    const float* adp = a_dst + h * 8;
    float s = 0.f, d = 0.f;
#pragma unroll
    for (int q = 0; q < 4; q++) {
        float2 f = __bfloat1622float2(hp[q]);
        s += f.x * asp[2 * q] + f.y * asp[2 * q + 1];
        d += f.x * adp[2 * q] + f.y * adp[2 * q + 1];
    }
    g_as1[i] = s;
    g_ad1[i] = d;
}

// ---------------- layer-1 gather: 8 lanes per dst node, lane = head --------
__global__ __launch_bounds__(256) void gather1_kernel(const float* __restrict__ b1) {
    int gid = blockIdx.x * blockDim.x + threadIdx.x;
    int n = gid >> 3;
    if (n >= NN) return;
    int h = gid & 7;                 // this lane's head
    float ad_h = g_ad1[n * 8 + h];
    int st = g_start[n];
    int deg = g_cnt[n];
    float acc[8];
#pragma unroll
    for (int j = 0; j < 8; j++) acc[j] = 0.f;
    float den = 0.f;
    for (int i = 0; i < deg; i++) {
        int s = g_csr[st + i];
        float w = lrexp(g_as1[s * 8 + h] + ad_h);
        uint4 raw = *reinterpret_cast<const uint4*>(g_h1b + (size_t)s * 64 + h * 8);
        const __nv_bfloat162* fp = reinterpret_cast<const __nv_bfloat162*>(&raw);
#pragma unroll
        for (int q = 0; q < 4; q++) {
            float2 f = __bfloat1622float2(fp[q]);
            acc[2 * q] += w * f.x;
            acc[2 * q + 1] += w * f.y;
        }
        den += w;
    }
    // self loop
    {
        float w = lrexp(g_as1[n * 8 + h] + ad_h);
        uint4 raw = *reinterpret_cast<const uint4*>(g_h1b + (size_t)n * 64 + h * 8);
        const __nv_bfloat162* fp = reinterpret_cast<const __nv_bfloat162*>(&raw);
#pragma unroll
        for (int q = 0; q < 4; q++) {
            float2 f = __bfloat1622float2(fp[q]);
            acc[2 * q] += w * f.x;
            acc[2 * q + 1] += w * f.y;
        }
        den += w;
    }
    float inv = 1.0f / (den + 1e-16f);
    float4 bv0 = *reinterpret_cast<const float4*>(b1 + h * 8);
    float4 bv1 = *reinterpret_cast<const float4*>(b1 + h * 8 + 4);
    float* op = g_out1 + (size_t)n * 64 + h * 8;
    *reinterpret_cast<float4*>(op) =
        make_float4(acc[0] * inv + bv0.x, acc[1] * inv + bv0.y,
                    acc[2] * inv + bv0.z, acc[3] * inv + bv0.w);
    *reinterpret_cast<float4*>(op + 4) =
        make_float4(acc[4] * inv + bv1.x, acc[5] * inv + bv1.y,
                    acc[6] * inv + bv1.z, acc[7] * inv + bv1.w);
}

// ---------------- layer-2 transform ----------------
__global__ __launch_bounds__(128) void gemm2_kernel(const float* __restrict__ W2,
                                                    const float* __restrict__ a_src,
                                                    const float* __restrict__ a_dst) {
    __shared__ float sW[448];
    __shared__ float sa[7], sd[7];
    int t = threadIdx.x;
    for (int j = t; j < 448; j += blockDim.x) sW[j] = W2[j];
    if (t < 7) { sa[t] = a_src[t]; sd[t] = a_dst[t]; }
    __syncthreads();
    int n = blockIdx.x * blockDim.x + t;
    if (n >= NN) return;
    float v[64];
    const float4* row = (const float4*)g_out1 + (size_t)n * 16;
#pragma unroll
    for (int q = 0; q < 16; q++) {
        float4 x = row[q];
        v[4 * q] = x.x; v[4 * q + 1] = x.y; v[4 * q + 2] = x.z; v[4 * q + 3] = x.w;
    }
    float h[7] = {0.f, 0.f, 0.f, 0.f, 0.f, 0.f, 0.f};
#pragma unroll 8
    for (int k = 0; k < 64; k++) {
        float vk = v[k];
#pragma unroll
        for (int c = 0; c < 7; c++) h[c] += vk * sW[k * 7 + c];
    }
    float s = 0.f, d = 0.f;
#pragma unroll
    for (int c = 0; c < 7; c++) { s += h[c] * sa[c]; d += h[c] * sd[c]; }
    float* hp = g_h2 + (size_t)n * 8;
#pragma unroll
    for (int c = 0; c < 7; c++) hp[c] = h[c];
    hp[7] = 1.0f;
    g_as2[n] = s;
    g_ad2[n] = d;
}

// ---------------- layer-2 gather (fused finalize + log_softmax) ------------
__global__ __launch_bounds__(256) void gather2_kernel(const float* __restrict__ b2,
                                                      float* __restrict__ out) {
    int gid = blockIdx.x * blockDim.x + threadIdx.x;
    int n = gid >> 3;
    if (n >= NN) return;
    int c = gid & 7;
    float ad = g_ad2[n];
    int st = g_start[n];
    int deg = g_cnt[n];
    float acc = 0.f;
    int i = 0;
    for (; i + 2 <= deg; i += 2) {
        int s0 = g_csr[st + i];
        int s1 = g_csr[st + i + 1];
        float w0 = lrexp(g_as2[s0] + ad);
        float w1 = lrexp(g_as2[s1] + ad);
        acc += w0 * g_h2[(size_t)s0 * 8 + c] + w1 * g_h2[(size_t)s1 * 8 + c];
    }
    if (i < deg) {
        int s0 = g_csr[st + i];
        float w0 = lrexp(g_as2[s0] + ad);
        acc += w0 * g_h2[(size_t)s0 * 8 + c];
    }
    float wself = lrexp(g_as2[n] + ad);
    acc += wself * g_h2[(size_t)n * 8 + c];
    float den = __shfl_sync(0xffffffffu, acc, (threadIdx.x & ~7) | 7);
    float inv = 1.0f / (den + 1e-16f);
    float o = (c < 7) ? (acc * inv + b2[c]) : -1e30f;
    float m = o;
#pragma unroll
    for (int off = 1; off < 8; off <<= 1)
        m = fmaxf(m, __shfl_xor_sync(0xffffffffu, m, off));
    float ex = (c < 7) ? __expf(o - m) : 0.f;
    float sum = ex;
#pragma unroll
    for (int off = 1; off < 8; off <<= 1)
        sum += __shfl_xor_sync(0xffffffffu, sum, off);
    float lse = m + logf(sum);
    if (c < 7) out[(size_t)n * 7 + c] = o - lse;
}

// ---------------- launcher ----------------
extern "C" void kernel_launch(void* const* d_in, const int* in_sizes, int n_in,
                              void* d_out, int out_size) {
    const float* x    = (const float*)d_in[0];
    const int*   ei   = (const int*)d_in[1];
    const float* W1   = (const float*)d_in[2];
    const float* as1  = (const float*)d_in[3];
    const float* ad1  = (const float*)d_in[4];
    const float* b1   = (const float*)d_in[5];
    const float* W2   = (const float*)d_in[6];
    const float* as2  = (const float*)d_in[7];
    const float* ad2  = (const float*)d_in[8];
    const float* b2   = (const float*)d_in[9];
    float* out = (float*)d_out;
    int E = in_sizes[1] / 2;
    const int* src = ei;
    const int* dst = ei + E;

    prep_kernel<<<(NN + 255) / 256, 256>>>(W1);
    hist_kernel<<<(E + 255) / 256, 256>>>(dst, E);
    scan1_kernel<<<NBLK, 256>>>();
    scan3_kernel<<<(NN + 255) / 256, 256>>>();
    scatter_kernel<<<(E + 255) / 256, 256>>>(src, dst, E);

    sgemm1_mma_kernel<<<(NN + 127) / 128, 256>>>(x);
    alpha1_kernel<<<(NN * 8 + 255) / 256, 256>>>(as1, ad1);
    gather1_kernel<<<(NN * 8 + 255) / 256, 256>>>(b1);
    gemm2_kernel<<<(NN + 127) / 128, 128>>>(W2, as2, ad2);
    gather2_kernel<<<(NN * 8 + 255) / 256, 256>>>(b2, out);
}